// round 1
// baseline (speedup 1.0000x reference)
#include <cuda_runtime.h>

#define WARPS 8
#define THREADS 256
#define NSTEP 10

// ---- f32x2 / FSET helpers (sm_103a packed fp32 path, PTX-only) ----
__device__ __forceinline__ float setgt1(float a) {
    float r;
    asm("set.gt.f32.f32 %0, %1, %2;" : "=f"(r) : "f"(a), "f"(1.0f));
    return r;
}
__device__ __forceinline__ unsigned long long fma2(unsigned long long a,
                                                   unsigned long long b,
                                                   unsigned long long c) {
    unsigned long long d;
    asm("fma.rn.f32x2 %0, %1, %2, %3;" : "=l"(d) : "l"(a), "l"(b), "l"(c));
    return d;
}
__device__ __forceinline__ unsigned long long pack2(float lo, float hi) {
    unsigned long long d;
    asm("mov.b64 %0, {%1, %2};" : "=l"(d) : "f"(lo), "f"(hi));
    return d;
}
__device__ __forceinline__ void unpack2(unsigned long long v, float& lo, float& hi) {
    asm("mov.b64 {%0, %1}, %2;" : "=f"(lo), "=f"(hi) : "l"(v));
}

// One warp per sample. Elements processed as 1024 pairs (2q, 2q+1); each lane
// owns 32 pairs. Layer-1 membrane kept in a single f32x2 register pair; the
// 10 per-step spike vectors are folded straight into 10 packed partial dot
// products against fc_w rows. Warp-reduce, then lane 0 runs the 2-channel
// layer-2 recurrence and writes the spike-count output.
__global__ void __launch_bounds__(THREADS)
snn_kernel(const float* __restrict__ x, const float* __restrict__ convw,
           const float* __restrict__ convb, const float* __restrict__ fcw,
           const float* __restrict__ fcb, float* __restrict__ out, int nB)
{
    // padded 18x18 input tile per warp (halo of zeros; origin shifted +1 so
    // all float2 tap loads land on 8B-aligned even indices)
    __shared__ __align__(16) float sx[WARPS][18 * 18];
    __shared__ __align__(16) float sw0[2048];
    __shared__ __align__(16) float sw1[2048];
    __shared__ float scw[72];
    __shared__ float scb[8];

    const int tid  = threadIdx.x;
    const int warp = tid >> 5;
    const int lane = tid & 31;
    const long long b = (long long)blockIdx.x * WARPS + warp;

    // stage fc_w (2x2048), conv weights, conv bias
    for (int i = tid; i < 2048; i += THREADS) {
        sw0[i] = fcw[i];
        sw1[i] = fcw[2048 + i];
    }
    if (tid < 72) scw[tid] = convw[tid];
    if (tid < 8)  scb[tid] = convb[tid];

    float* sxw = sx[warp];
    #pragma unroll
    for (int i = lane; i < 18 * 18; i += 32) sxw[i] = 0.0f;
    __syncwarp();

    if (b < nB) {
        const float4* xb = (const float4*)(x + b * 256);
        #pragma unroll
        for (int i = lane; i < 64; i += 32) {
            float4 v = xb[i];
            int p = i * 4;
            int y = p >> 4, xx = p & 15;
            float* d = &sxw[(y + 1) * 18 + xx + 1];
            d[0] = v.x; d[1] = v.y; d[2] = v.z; d[3] = v.w;
        }
    }
    __syncthreads();

    if (b < nB) {
        // 10 time steps x 2 output channels of packed partial sums
        unsigned long long A0[NSTEP], A1[NSTEP];
        #pragma unroll
        for (int t = 0; t < NSTEP; t++) { A0[t] = 0ull; A1[t] = 0ull; }

        const unsigned long long BETA2  = 0x3F6666663F666666ull; // (0.9f, 0.9f)
        const unsigned long long NEG1_2 = 0xBF800000BF800000ull; // (-1.f, -1.f)

        #pragma unroll 1
        for (int ch = 0; ch < 8; ch++) {
            float w[9];
            #pragma unroll
            for (int k = 0; k < 9; k++) w[k] = scw[ch * 9 + k];
            const float cbias = scb[ch];

            #pragma unroll 1
            for (int rr = 0; rr < 4; rr++) {
                const int q  = lane + 32 * rr;   // pair index in channel, 0..127
                const int y  = q >> 3;           // row 0..15
                const int x0 = (q & 7) * 2;      // even col
                const float* rp = sxw + y * 18 + x0;
                // 3 rows x 4 cols of taps, as aligned float2s
                float2 t00 = *(const float2*)(rp);
                float2 t01 = *(const float2*)(rp + 2);
                float2 t10 = *(const float2*)(rp + 18);
                float2 t11 = *(const float2*)(rp + 20);
                float2 t20 = *(const float2*)(rp + 36);
                float2 t21 = *(const float2*)(rp + 38);

                float ca = cbias, cbv = cbias;
                ca = fmaf(w[0], t00.x, ca);  cbv = fmaf(w[0], t00.y, cbv);
                ca = fmaf(w[1], t00.y, ca);  cbv = fmaf(w[1], t01.x, cbv);
                ca = fmaf(w[2], t01.x, ca);  cbv = fmaf(w[2], t01.y, cbv);
                ca = fmaf(w[3], t10.x, ca);  cbv = fmaf(w[3], t10.y, cbv);
                ca = fmaf(w[4], t10.y, ca);  cbv = fmaf(w[4], t11.x, cbv);
                ca = fmaf(w[5], t11.x, ca);  cbv = fmaf(w[5], t11.y, cbv);
                ca = fmaf(w[6], t20.x, ca);  cbv = fmaf(w[6], t20.y, cbv);
                ca = fmaf(w[7], t20.y, ca);  cbv = fmaf(w[7], t21.x, cbv);
                ca = fmaf(w[8], t21.x, ca);  cbv = fmaf(w[8], t21.y, cbv);

                const int ib = ch * 256 + q * 2;          // flat element idx (even)
                const unsigned long long w0p = *(const unsigned long long*)&sw0[ib];
                const unsigned long long w1p = *(const unsigned long long*)&sw1[ib];
                const unsigned long long c2  = pack2(ca, cbv);

                unsigned long long m2 = 0ull, s2 = 0ull;
                #pragma unroll
                for (int t = 0; t < NSTEP; t++) {
                    m2 = fma2(BETA2, m2, c2);   // beta*m + c
                    m2 = fma2(s2, NEG1_2, m2);  // - reset (prev spike)
                    float ma, mb;
                    unpack2(m2, ma, mb);
                    s2 = pack2(setgt1(ma), setgt1(mb));   // spk = (m > 1)
                    A0[t] = fma2(s2, w0p, A0[t]);
                    A1[t] = fma2(s2, w1p, A1[t]);
                }
            }
        }

        // fold pair halves, then warp-reduce the 20 partial sums
        float r0[NSTEP], r1[NSTEP];
        #pragma unroll
        for (int t = 0; t < NSTEP; t++) {
            float a, c;
            unpack2(A0[t], a, c); r0[t] = a + c;
            unpack2(A1[t], a, c); r1[t] = a + c;
        }
        #pragma unroll
        for (int off = 16; off > 0; off >>= 1) {
            #pragma unroll
            for (int t = 0; t < NSTEP; t++) {
                r0[t] += __shfl_down_sync(0xffffffffu, r0[t], off);
                r1[t] += __shfl_down_sync(0xffffffffu, r1[t], off);
            }
        }

        if (lane == 0) {
            const float fb0 = fcb[0], fb1 = fcb[1];
            float m20 = 0.f, m21 = 0.f, s20 = 0.f, s21 = 0.f, o0 = 0.f, o1 = 0.f;
            #pragma unroll
            for (int t = 0; t < NSTEP; t++) {
                float c0 = r0[t] + fb0;
                float c1 = r1[t] + fb1;
                m20 = fmaf(0.9f, m20, c0) - s20;
                m21 = fmaf(0.9f, m21, c1) - s21;
                s20 = (m20 > 1.0f) ? 1.0f : 0.0f;
                s21 = (m21 > 1.0f) ? 1.0f : 0.0f;
                o0 += s20;
                o1 += s21;
            }
            out[b * 2 + 0] = o0;
            out[b * 2 + 1] = o1;
        }
    }
}

extern "C" void kernel_launch(void* const* d_in, const int* in_sizes, int n_in,
                              void* d_out, int out_size) {
    const float* x  = (const float*)d_in[0];
    const float* cw = (const float*)d_in[1];
    const float* cb = (const float*)d_in[2];
    const float* fw = (const float*)d_in[3];
    const float* fb = (const float*)d_in[4];
    float* out = (float*)d_out;

    const int nB = in_sizes[0] / 256;
    const int blocks = (nB + WARPS - 1) / WARPS;
    snn_kernel<<<blocks, THREADS>>>(x, cw, cb, fw, fb, out, nB);
}